// round 3
// baseline (speedup 1.0000x reference)
#include <cuda_runtime.h>
#include <math_constants.h>

#define BATCH 2
#define T_SEQ 2048
#define CD 1024
#define HS 64
#define NH 16
#define MROWS (BATCH * T_SEQ)   /* 4096 */

// Scratch (static device allocations are allowed; cudaMalloc is not)
__device__ float g_q[MROWS * CD];   // projected q, raw [4096,1024]
__device__ float g_k[MROWS * HS];   // [4096,64]
__device__ float g_v[MROWS * HS];   // [4096,64]
__device__ float g_y[MROWS * CD];   // attention output, [B,T,C] layout

// ---------------------------------------------------------------------------
// Fused QKV projection: out[:,0:1024]=X@Wq^T, [1024:1088]=X@Wk^T, [1088:1152]=X@Wv^T
// Tile 128x128x8, 256 threads, 8x8 per thread (two 64-wide half-tiles).
// ---------------------------------------------------------------------------
__global__ __launch_bounds__(256, 2)
void qkv_gemm(const float* __restrict__ X, const float* __restrict__ Wq,
              const float* __restrict__ Wk, const float* __restrict__ Wv) {
    __shared__ float As[8][128];
    __shared__ float Bs[8][128];
    const int tid = threadIdx.x;
    const int bm = blockIdx.y * 128;
    const int bn = blockIdx.x * 128;          // 0..1151 in steps of 128
    const int tx = tid & 15;
    const int ty = tid >> 4;
    const int lr = tid >> 1;                  // 0..127
    const int lk = (tid & 1) * 4;             // 0 or 4

    const float* Ag = X + (bm + lr) * CD + lk;
    const int n = bn + lr;
    const float* wrow;
    if (n < 1024)      wrow = Wq + n * CD;
    else if (n < 1088) wrow = Wk + (n - 1024) * CD;
    else               wrow = Wv + (n - 1088) * CD;
    wrow += lk;

    float acc[8][8];
    #pragma unroll
    for (int i = 0; i < 8; i++)
        #pragma unroll
        for (int j = 0; j < 8; j++) acc[i][j] = 0.f;

    for (int k0 = 0; k0 < CD; k0 += 8) {
        float4 av = *(const float4*)(Ag + k0);
        float4 wv = *(const float4*)(wrow + k0);
        As[lk+0][lr] = av.x; As[lk+1][lr] = av.y; As[lk+2][lr] = av.z; As[lk+3][lr] = av.w;
        Bs[lk+0][lr] = wv.x; Bs[lk+1][lr] = wv.y; Bs[lk+2][lr] = wv.z; Bs[lk+3][lr] = wv.w;
        __syncthreads();
        #pragma unroll
        for (int kk = 0; kk < 8; kk++) {
            float a[8], b[8];
            *(float4*)(a)     = *(const float4*)&As[kk][ty * 4];
            *(float4*)(a + 4) = *(const float4*)&As[kk][64 + ty * 4];
            *(float4*)(b)     = *(const float4*)&Bs[kk][tx * 4];
            *(float4*)(b + 4) = *(const float4*)&Bs[kk][64 + tx * 4];
            #pragma unroll
            for (int i = 0; i < 8; i++)
                #pragma unroll
                for (int j = 0; j < 8; j++)
                    acc[i][j] = fmaf(a[i], b[j], acc[i][j]);
        }
        __syncthreads();
    }

    #pragma unroll
    for (int ih = 0; ih < 2; ih++)
    #pragma unroll
    for (int i = 0; i < 4; i++) {
        const int r = bm + ih * 64 + ty * 4 + i;
        #pragma unroll
        for (int jh = 0; jh < 2; jh++) {
            const int c = bn + jh * 64 + tx * 4;
            float4 o;
            o.x = acc[ih * 4 + i][jh * 4 + 0];
            o.y = acc[ih * 4 + i][jh * 4 + 1];
            o.z = acc[ih * 4 + i][jh * 4 + 2];
            o.w = acc[ih * 4 + i][jh * 4 + 3];
            if (c < 1024)      *(float4*)(g_q + r * CD + c) = o;
            else if (c < 1088) *(float4*)(g_k + r * HS + (c - 1024)) = o;
            else               *(float4*)(g_v + r * HS + (c - 1088)) = o;
        }
    }
}

// ---------------------------------------------------------------------------
// Causal MQA flash attention, fp32. Grid (16 q-tiles, 32 b*h), 128 threads.
// One thread owns one query row: q[64] and O[64] in registers.
// Torch-faithful reshape: Q for head h = g_q[b*T*C + h*T*hs ...] viewed [T,hs].
// ---------------------------------------------------------------------------
__global__ __launch_bounds__(128, 2)
void mqa_attn() {
    __shared__ float Ks[32 * 64];
    __shared__ float Vs[32 * 64];
    const int tid = threadIdx.x;
    const int bh = blockIdx.y;
    const int b = bh >> 4;
    const int h = bh & 15;
    const int qt = (int)gridDim.x - 1 - (int)blockIdx.x;  // big tiles first
    const int gq = qt * 128 + tid;

    const float* Q = g_q + b * T_SEQ * CD + h * T_SEQ * HS;
    const float4* kg = (const float4*)(g_k + b * T_SEQ * HS);
    const float4* vg = (const float4*)(g_v + b * T_SEQ * HS);

    float4 qv[16];
    const float4* qrow = (const float4*)(Q + gq * HS);
    #pragma unroll
    for (int d = 0; d < 16; d++) {
        float4 t = qrow[d];
        t.x *= 0.125f; t.y *= 0.125f; t.z *= 0.125f; t.w *= 0.125f;  // hs^-0.5
        qv[d] = t;
    }

    float4 O4[16];
    #pragma unroll
    for (int d = 0; d < 16; d++) O4[d] = make_float4(0.f, 0.f, 0.f, 0.f);
    float m = -CUDART_INF_F;
    float l = 0.f;

    const int ntiles = qt * 4 + 4;   // 32-key tiles covering keys <= qt*128+127

    #pragma unroll 1
    for (int kt = 0; kt < ntiles; kt++) {
        __syncthreads();
        for (int idx = tid; idx < 512; idx += 128) {
            ((float4*)Ks)[idx] = kg[kt * 512 + idx];
            ((float4*)Vs)[idx] = vg[kt * 512 + idx];
        }
        __syncthreads();

        #pragma unroll 1
        for (int c = 0; c < 2; c++) {
            const int kbase = kt * 32 + c * 16;
            float s[16];
            #pragma unroll
            for (int j = 0; j < 16; j++) {
                const float4* kr = (const float4*)(Ks + (c * 16 + j) * 64);
                float acc = 0.f;
                #pragma unroll
                for (int d = 0; d < 16; d++) {
                    float4 kd = kr[d];
                    acc = fmaf(qv[d].x, kd.x, acc);
                    acc = fmaf(qv[d].y, kd.y, acc);
                    acc = fmaf(qv[d].z, kd.z, acc);
                    acc = fmaf(qv[d].w, kd.w, acc);
                }
                s[j] = acc;
            }
            if (kbase + 15 > gq) {                 // causal mask (diagonal tiles only)
                #pragma unroll
                for (int j = 0; j < 16; j++)
                    if (kbase + j > gq) s[j] = -CUDART_INF_F;
            }
            float mn = m;
            #pragma unroll
            for (int j = 0; j < 16; j++) mn = fmaxf(mn, s[j]);
            const float corr = __expf(m - mn);
            m = mn;
            l *= corr;
            #pragma unroll
            for (int d = 0; d < 16; d++) {
                O4[d].x *= corr; O4[d].y *= corr; O4[d].z *= corr; O4[d].w *= corr;
            }
            #pragma unroll
            for (int j = 0; j < 16; j++) {
                const float p = __expf(s[j] - mn);
                l += p;
                const float4* vr = (const float4*)(Vs + (c * 16 + j) * 64);
                #pragma unroll
                for (int d = 0; d < 16; d++) {
                    float4 vd = vr[d];
                    O4[d].x = fmaf(p, vd.x, O4[d].x);
                    O4[d].y = fmaf(p, vd.y, O4[d].y);
                    O4[d].z = fmaf(p, vd.z, O4[d].z);
                    O4[d].w = fmaf(p, vd.w, O4[d].w);
                }
            }
        }
    }

    const float inv = 1.0f / l;
    // transpose(0,2,1,3): y[b, t=gq, h*64+d]
    float4* yo = (float4*)(g_y + b * T_SEQ * CD + gq * CD + h * HS);
    #pragma unroll
    for (int d = 0; d < 16; d++) {
        float4 o = O4[d];
        o.x *= inv; o.y *= inv; o.z *= inv; o.w *= inv;
        yo[d] = o;
    }
}

// ---------------------------------------------------------------------------
// Output projection: out = g_y @ Wp^T + bp. Same 128x128x8 tile.
// ---------------------------------------------------------------------------
__global__ __launch_bounds__(256, 2)
void out_gemm(const float* __restrict__ Wp, const float* __restrict__ bp,
              float* __restrict__ out) {
    __shared__ float As[8][128];
    __shared__ float Bs[8][128];
    const int tid = threadIdx.x;
    const int bm = blockIdx.y * 128;
    const int bn = blockIdx.x * 128;
    const int tx = tid & 15;
    const int ty = tid >> 4;
    const int lr = tid >> 1;
    const int lk = (tid & 1) * 4;

    const float* Ag = g_y + (bm + lr) * CD + lk;
    const float* Wg = Wp + (bn + lr) * CD + lk;

    float acc[8][8];
    #pragma unroll
    for (int i = 0; i < 8; i++)
        #pragma unroll
        for (int j = 0; j < 8; j++) acc[i][j] = 0.f;

    for (int k0 = 0; k0 < CD; k0 += 8) {
        float4 av = *(const float4*)(Ag + k0);
        float4 wv = *(const float4*)(Wg + k0);
        As[lk+0][lr] = av.x; As[lk+1][lr] = av.y; As[lk+2][lr] = av.z; As[lk+3][lr] = av.w;
        Bs[lk+0][lr] = wv.x; Bs[lk+1][lr] = wv.y; Bs[lk+2][lr] = wv.z; Bs[lk+3][lr] = wv.w;
        __syncthreads();
        #pragma unroll
        for (int kk = 0; kk < 8; kk++) {
            float a[8], b[8];
            *(float4*)(a)     = *(const float4*)&As[kk][ty * 4];
            *(float4*)(a + 4) = *(const float4*)&As[kk][64 + ty * 4];
            *(float4*)(b)     = *(const float4*)&Bs[kk][tx * 4];
            *(float4*)(b + 4) = *(const float4*)&Bs[kk][64 + tx * 4];
            #pragma unroll
            for (int i = 0; i < 8; i++)
                #pragma unroll
                for (int j = 0; j < 8; j++)
                    acc[i][j] = fmaf(a[i], b[j], acc[i][j]);
        }
        __syncthreads();
    }

    #pragma unroll
    for (int ih = 0; ih < 2; ih++)
    #pragma unroll
    for (int i = 0; i < 4; i++) {
        const int r = bm + ih * 64 + ty * 4 + i;
        #pragma unroll
        for (int jh = 0; jh < 2; jh++) {
            const int c = bn + jh * 64 + tx * 4;
            float4 o;
            o.x = acc[ih * 4 + i][jh * 4 + 0] + bp[c + 0];
            o.y = acc[ih * 4 + i][jh * 4 + 1] + bp[c + 1];
            o.z = acc[ih * 4 + i][jh * 4 + 2] + bp[c + 2];
            o.w = acc[ih * 4 + i][jh * 4 + 3] + bp[c + 3];
            *(float4*)(out + r * CD + c) = o;
        }
    }
}

// ---------------------------------------------------------------------------
// Inputs (metadata order): x, Wk, Wv, Wq, Wp, bp. Output: float32 [B,T,C].
// ---------------------------------------------------------------------------
extern "C" void kernel_launch(void* const* d_in, const int* in_sizes, int n_in,
                              void* d_out, int out_size) {
    const float* x  = (const float*)d_in[0];
    const float* Wk = (const float*)d_in[1];
    const float* Wv = (const float*)d_in[2];
    const float* Wq = (const float*)d_in[3];
    const float* Wp = (const float*)d_in[4];
    const float* bp = (const float*)d_in[5];
    float* out = (float*)d_out;
    (void)in_sizes; (void)n_in; (void)out_size;

    qkv_gemm<<<dim3(9, 32), 256>>>(x, Wq, Wk, Wv);   // 1152 cols = q|k|v
    mqa_attn<<<dim3(16, 32), 128>>>();
    out_gemm<<<dim3(8, 32), 256>>>(Wp, bp, out);
}

// round 8
// speedup vs baseline: 2.3375x; 2.3375x over previous
#include <cuda_runtime.h>
#include <math_constants.h>

#define BATCH 2
#define T_SEQ 2048
#define CD 1024
#define HS 64
#define NH 16
#define MROWS (BATCH * T_SEQ)   /* 4096 */

// Scratch
__device__ float g_q[MROWS * CD];   // projected q, raw [4096,1024]
__device__ float g_k[MROWS * HS];   // [4096,64]
__device__ float g_v[MROWS * HS];   // [4096,64]
__device__ float g_y[MROWS * CD];   // attention output, [B,T,C]

__device__ __forceinline__ unsigned f2tf(float f) {
    unsigned u; asm("cvt.rna.tf32.f32 %0, %1;" : "=r"(u) : "f"(f)); return u;
}
__device__ __forceinline__ void mma_tf32(float* c, const unsigned* a, unsigned b0, unsigned b1) {
    asm volatile("mma.sync.aligned.m16n8k8.row.col.f32.tf32.tf32.f32 "
        "{%0,%1,%2,%3}, {%4,%5,%6,%7}, {%8,%9}, {%0,%1,%2,%3};"
        : "+f"(c[0]), "+f"(c[1]), "+f"(c[2]), "+f"(c[3])
        : "r"(a[0]), "r"(a[1]), "r"(a[2]), "r"(a[3]), "r"(b0), "r"(b1));
}

// ---------------------------------------------------------------------------
// Fused QKV projection (tf32 tensor cores): cols 0:1024=X@Wq^T, 1024:1088=Wk, 1088:1152=Wv
// 128x128 block tile, 8 warps (4x2), warp tile 32x64, K-chunk 16.
// ---------------------------------------------------------------------------
__global__ __launch_bounds__(256, 2)
void qkv_gemm_tc(const float* __restrict__ X, const float* __restrict__ Wq,
                 const float* __restrict__ Wk, const float* __restrict__ Wv) {
    __shared__ float As[16][136];   // [k][m] transposed, pad -> 8k+m banks
    __shared__ float Bs[128][20];   // [n][k], pad 20 -> conflict-free frags
    const int tid  = threadIdx.x;
    const int warp = tid >> 5, lane = tid & 31;
    const int ql = lane >> 2, qd = lane & 3;
    const int wm = (warp >> 1) * 32;     // warp M offset in tile
    const int wn = (warp & 1) * 64;      // warp N offset in tile
    const int bm = blockIdx.y * 128;
    const int bn = blockIdx.x * 128;     // 0..1151

    // per-thread gmem staging coords: f = tid + i*256, row = f>>2, k4 = (f&3)*4
    const float* aptr[2];
    const float* bptr[2];
    int arow[2], brow[2], ak4[2], bk4[2];
    #pragma unroll
    for (int i = 0; i < 2; i++) {
        int f = tid + i * 256;
        arow[i] = f >> 2; ak4[i] = (f & 3) << 2;
        brow[i] = arow[i]; bk4[i] = ak4[i];
        aptr[i] = X + (bm + arow[i]) * CD + ak4[i];
        int n = bn + brow[i];
        const float* wr;
        if (n < 1024)      wr = Wq + n * CD;
        else if (n < 1088) wr = Wk + (n - 1024) * CD;
        else               wr = Wv + (n - 1088) * CD;
        bptr[i] = wr + bk4[i];
    }

    float acc[2][8][4];
    #pragma unroll
    for (int mi = 0; mi < 2; mi++)
        #pragma unroll
        for (int nb = 0; nb < 8; nb++)
            #pragma unroll
            for (int j = 0; j < 4; j++) acc[mi][nb][j] = 0.f;

    float4 ra[2], rb[2];
    #pragma unroll
    for (int i = 0; i < 2; i++) { ra[i] = *(const float4*)aptr[i]; rb[i] = *(const float4*)bptr[i]; }

    for (int kc = 0; kc < CD / 16; kc++) {
        #pragma unroll
        for (int i = 0; i < 2; i++) {
            As[ak4[i]+0][arow[i]] = __uint_as_float(f2tf(ra[i].x));
            As[ak4[i]+1][arow[i]] = __uint_as_float(f2tf(ra[i].y));
            As[ak4[i]+2][arow[i]] = __uint_as_float(f2tf(ra[i].z));
            As[ak4[i]+3][arow[i]] = __uint_as_float(f2tf(ra[i].w));
            Bs[brow[i]][bk4[i]+0] = __uint_as_float(f2tf(rb[i].x));
            Bs[brow[i]][bk4[i]+1] = __uint_as_float(f2tf(rb[i].y));
            Bs[brow[i]][bk4[i]+2] = __uint_as_float(f2tf(rb[i].z));
            Bs[brow[i]][bk4[i]+3] = __uint_as_float(f2tf(rb[i].w));
        }
        __syncthreads();
        if (kc + 1 < CD / 16) {
            #pragma unroll
            for (int i = 0; i < 2; i++) {
                ra[i] = *(const float4*)(aptr[i] + (kc + 1) * 16);
                rb[i] = *(const float4*)(bptr[i] + (kc + 1) * 16);
            }
        }
        #pragma unroll
        for (int kk = 0; kk < 2; kk++) {
            unsigned a[2][4];
            #pragma unroll
            for (int mi = 0; mi < 2; mi++) {
                a[mi][0] = __float_as_uint(As[kk*8 + qd    ][wm + mi*16 + ql    ]);
                a[mi][1] = __float_as_uint(As[kk*8 + qd    ][wm + mi*16 + ql + 8]);
                a[mi][2] = __float_as_uint(As[kk*8 + qd + 4][wm + mi*16 + ql    ]);
                a[mi][3] = __float_as_uint(As[kk*8 + qd + 4][wm + mi*16 + ql + 8]);
            }
            #pragma unroll
            for (int nb = 0; nb < 8; nb++) {
                unsigned b0 = __float_as_uint(Bs[wn + nb*8 + ql][kk*8 + qd    ]);
                unsigned b1 = __float_as_uint(Bs[wn + nb*8 + ql][kk*8 + qd + 4]);
                mma_tf32(acc[0][nb], a[0], b0, b1);
                mma_tf32(acc[1][nb], a[1], b0, b1);
            }
        }
        __syncthreads();
    }

    #pragma unroll
    for (int mi = 0; mi < 2; mi++) {
        const int r0 = bm + wm + mi*16 + ql;
        #pragma unroll
        for (int nb = 0; nb < 8; nb++) {
            const int c = bn + wn + nb*8 + 2*qd;
            float2 lo = make_float2(acc[mi][nb][0], acc[mi][nb][1]);
            float2 hi = make_float2(acc[mi][nb][2], acc[mi][nb][3]);
            if (c < 1024) {
                *(float2*)(g_q + r0 * CD + c)       = lo;
                *(float2*)(g_q + (r0 + 8) * CD + c) = hi;
            } else if (c < 1088) {
                *(float2*)(g_k + r0 * HS + (c - 1024))       = lo;
                *(float2*)(g_k + (r0 + 8) * HS + (c - 1024)) = hi;
            } else {
                *(float2*)(g_v + r0 * HS + (c - 1088))       = lo;
                *(float2*)(g_v + (r0 + 8) * HS + (c - 1088)) = hi;
            }
        }
    }
}

// ---------------------------------------------------------------------------
// Causal MQA flash attention on tensor cores (tf32 mma, fp32 softmax).
// Grid (16 q-blocks, 32 b*h), 256 threads = 8 warps, warp = 16 query rows.
// ---------------------------------------------------------------------------
__global__ __launch_bounds__(256, 1)
void mqa_attn_tc() {
    __shared__ float Ks[64][68];   // pad 68: S-phase B-frag conflict-free
    __shared__ float Vs[64][72];   // pad 72: PV-phase B-frag conflict-free
    const int tid = threadIdx.x;
    const int warp = tid >> 5, lane = tid & 31;
    const int ql = lane >> 2, qd = lane & 3;
    const int bh = blockIdx.y;
    const int b = bh >> 4, h = bh & 15;
    const int qt = 15 - (int)blockIdx.x;          // heavy tiles first
    const int row0 = qt * 128 + warp * 16;        // warp's first query row

    // Q fragments (torch-faithful view: head h = rows h*T..(h+1)*T of q matrix)
    const float* Q = g_q + (b * NH + h) * T_SEQ * HS;
    unsigned qa[8][4];
    {
        const int r0 = row0 + ql, r1 = r0 + 8;
        #pragma unroll
        for (int kk = 0; kk < 8; kk++) {
            const int c0 = kk * 8 + qd, c1 = c0 + 4;
            qa[kk][0] = f2tf(Q[r0 * HS + c0] * 0.125f);
            qa[kk][1] = f2tf(Q[r1 * HS + c0] * 0.125f);
            qa[kk][2] = f2tf(Q[r0 * HS + c1] * 0.125f);
            qa[kk][3] = f2tf(Q[r1 * HS + c1] * 0.125f);
        }
    }

    float o[8][4];
    #pragma unroll
    for (int nb = 0; nb < 8; nb++)
        #pragma unroll
        for (int j = 0; j < 4; j++) o[nb][j] = 0.f;
    float m0 = -CUDART_INF_F, m1 = -CUDART_INF_F, l0 = 0.f, l1 = 0.f;

    const float* kg = g_k + b * T_SEQ * HS;
    const float* vg = g_v + b * T_SEQ * HS;
    const int ntiles = qt * 2 + 2;   // 64-key tiles covering keys <= qt*128+127

    #pragma unroll 1
    for (int kt = 0; kt < ntiles; kt++) {
        __syncthreads();
        #pragma unroll
        for (int i = 0; i < 4; i++) {
            int f = tid + i * 256;           // 0..1023 : 64 rows x 16 float4
            int r = f >> 4;
            int c4 = (f & 15) << 2;
            float4 kq = *(const float4*)(kg + (kt * 64 + r) * HS + c4);
            float4 vq = *(const float4*)(vg + (kt * 64 + r) * HS + c4);
            Ks[r][c4+0] = __uint_as_float(f2tf(kq.x));
            Ks[r][c4+1] = __uint_as_float(f2tf(kq.y));
            Ks[r][c4+2] = __uint_as_float(f2tf(kq.z));
            Ks[r][c4+3] = __uint_as_float(f2tf(kq.w));
            Vs[r][c4+0] = __uint_as_float(f2tf(vq.x));
            Vs[r][c4+1] = __uint_as_float(f2tf(vq.y));
            Vs[r][c4+2] = __uint_as_float(f2tf(vq.z));
            Vs[r][c4+3] = __uint_as_float(f2tf(vq.w));
        }
        __syncthreads();

        // ---- S = Q K^T (16x64 per warp) ----
        float c[8][4];
        #pragma unroll
        for (int nb = 0; nb < 8; nb++)
            #pragma unroll
            for (int j = 0; j < 4; j++) c[nb][j] = 0.f;
        #pragma unroll
        for (int kk = 0; kk < 8; kk++) {
            #pragma unroll
            for (int nb = 0; nb < 8; nb++) {
                unsigned b0 = __float_as_uint(Ks[nb*8 + ql][kk*8 + qd    ]);
                unsigned b1 = __float_as_uint(Ks[nb*8 + ql][kk*8 + qd + 4]);
                mma_tf32(c[nb], qa[kk], b0, b1);
            }
        }

        // ---- causal mask ----
        if (kt * 64 + 63 > row0) {
            const int r0g = row0 + ql, r1g = r0g + 8;
            #pragma unroll
            for (int nb = 0; nb < 8; nb++) {
                const int col = kt * 64 + nb * 8 + 2 * qd;
                if (col     > r0g) c[nb][0] = -CUDART_INF_F;
                if (col + 1 > r0g) c[nb][1] = -CUDART_INF_F;
                if (col     > r1g) c[nb][2] = -CUDART_INF_F;
                if (col + 1 > r1g) c[nb][3] = -CUDART_INF_F;
            }
        }

        // ---- online softmax ----
        float mx0 = m0, mx1 = m1;
        #pragma unroll
        for (int nb = 0; nb < 8; nb++) {
            mx0 = fmaxf(mx0, fmaxf(c[nb][0], c[nb][1]));
            mx1 = fmaxf(mx1, fmaxf(c[nb][2], c[nb][3]));
        }
        mx0 = fmaxf(mx0, __shfl_xor_sync(0xffffffffu, mx0, 1));
        mx0 = fmaxf(mx0, __shfl_xor_sync(0xffffffffu, mx0, 2));
        mx1 = fmaxf(mx1, __shfl_xor_sync(0xffffffffu, mx1, 1));
        mx1 = fmaxf(mx1, __shfl_xor_sync(0xffffffffu, mx1, 2));
        const float corr0 = __expf(m0 - mx0);
        const float corr1 = __expf(m1 - mx1);
        m0 = mx0; m1 = mx1;
        l0 *= corr0; l1 *= corr1;
        #pragma unroll
        for (int nb = 0; nb < 8; nb++) {
            o[nb][0] *= corr0; o[nb][1] *= corr0;
            o[nb][2] *= corr1; o[nb][3] *= corr1;
        }
        #pragma unroll
        for (int nb = 0; nb < 8; nb++) {
            float p;
            p = __expf(c[nb][0] - mx0); l0 += p; c[nb][0] = __uint_as_float(f2tf(p));
            p = __expf(c[nb][1] - mx0); l0 += p; c[nb][1] = __uint_as_float(f2tf(p));
            p = __expf(c[nb][2] - mx1); l1 += p; c[nb][2] = __uint_as_float(f2tf(p));
            p = __expf(c[nb][3] - mx1); l1 += p; c[nb][3] = __uint_as_float(f2tf(p));
        }

        // ---- O += P V : convert P C-frags -> A-frags via quad shuffles ----
        const int src  = (lane & ~3) | (qd >> 1);
        const int src2 = src + 2;
        const bool oddc = (qd & 1);
        #pragma unroll
        for (int kk = 0; kk < 8; kk++) {
            float v00 = __shfl_sync(0xffffffffu, c[kk][0], src);
            float v01 = __shfl_sync(0xffffffffu, c[kk][1], src);
            float v10 = __shfl_sync(0xffffffffu, c[kk][2], src);
            float v11 = __shfl_sync(0xffffffffu, c[kk][3], src);
            float w00 = __shfl_sync(0xffffffffu, c[kk][0], src2);
            float w01 = __shfl_sync(0xffffffffu, c[kk][1], src2);
            float w10 = __shfl_sync(0xffffffffu, c[kk][2], src2);
            float w11 = __shfl_sync(0xffffffffu, c[kk][3], src2);
            unsigned a[4];
            a[0] = __float_as_uint(oddc ? v01 : v00);
            a[1] = __float_as_uint(oddc ? v11 : v10);
            a[2] = __float_as_uint(oddc ? w01 : w00);
            a[3] = __float_as_uint(oddc ? w11 : w10);
            #pragma unroll
            for (int nb = 0; nb < 8; nb++) {
                unsigned b0 = __float_as_uint(Vs[kk*8 + qd    ][nb*8 + ql]);
                unsigned b1 = __float_as_uint(Vs[kk*8 + qd + 4][nb*8 + ql]);
                mma_tf32(o[nb], a, b0, b1);
            }
        }
    }

    l0 += __shfl_xor_sync(0xffffffffu, l0, 1);
    l0 += __shfl_xor_sync(0xffffffffu, l0, 2);
    l1 += __shfl_xor_sync(0xffffffffu, l1, 1);
    l1 += __shfl_xor_sync(0xffffffffu, l1, 2);
    const float inv0 = 1.0f / l0, inv1 = 1.0f / l1;

    // transpose(0,2,1,3): y[b, t, h*64 + d]
    float* yb = g_y + b * T_SEQ * CD;
    const int r0g = row0 + ql, r1g = r0g + 8;
    #pragma unroll
    for (int nb = 0; nb < 8; nb++) {
        const int col = h * HS + nb * 8 + 2 * qd;
        *(float2*)(yb + r0g * CD + col) = make_float2(o[nb][0] * inv0, o[nb][1] * inv0);
        *(float2*)(yb + r1g * CD + col) = make_float2(o[nb][2] * inv1, o[nb][3] * inv1);
    }
}

// ---------------------------------------------------------------------------
// Output projection (tf32 tensor cores): out = g_y @ Wp^T + bp
// ---------------------------------------------------------------------------
__global__ __launch_bounds__(256, 2)
void out_gemm_tc(const float* __restrict__ Wp, const float* __restrict__ bp,
                 float* __restrict__ out) {
    __shared__ float As[16][136];
    __shared__ float Bs[128][20];
    const int tid  = threadIdx.x;
    const int warp = tid >> 5, lane = tid & 31;
    const int ql = lane >> 2, qd = lane & 3;
    const int wm = (warp >> 1) * 32;
    const int wn = (warp & 1) * 64;
    const int bm = blockIdx.y * 128;
    const int bn = blockIdx.x * 128;

    const float* aptr[2];
    const float* bptr[2];
    int arow[2], ak4[2];
    #pragma unroll
    for (int i = 0; i < 2; i++) {
        int f = tid + i * 256;
        arow[i] = f >> 2; ak4[i] = (f & 3) << 2;
        aptr[i] = g_y + (bm + arow[i]) * CD + ak4[i];
        bptr[i] = Wp + (bn + arow[i]) * CD + ak4[i];
    }

    float acc[2][8][4];
    #pragma unroll
    for (int mi = 0; mi < 2; mi++)
        #pragma unroll
        for (int nb = 0; nb < 8; nb++)
            #pragma unroll
            for (int j = 0; j < 4; j++) acc[mi][nb][j] = 0.f;

    float4 ra[2], rb[2];
    #pragma unroll
    for (int i = 0; i < 2; i++) { ra[i] = *(const float4*)aptr[i]; rb[i] = *(const float4*)bptr[i]; }

    for (int kc = 0; kc < CD / 16; kc++) {
        #pragma unroll
        for (int i = 0; i < 2; i++) {
            As[ak4[i]+0][arow[i]] = __uint_as_float(f2tf(ra[i].x));
            As[ak4[i]+1][arow[i]] = __uint_as_float(f2tf(ra[i].y));
            As[ak4[i]+2][arow[i]] = __uint_as_float(f2tf(ra[i].z));
            As[ak4[i]+3][arow[i]] = __uint_as_float(f2tf(ra[i].w));
            Bs[arow[i]][ak4[i]+0] = __uint_as_float(f2tf(rb[i].x));
            Bs[arow[i]][ak4[i]+1] = __uint_as_float(f2tf(rb[i].y));
            Bs[arow[i]][ak4[i]+2] = __uint_as_float(f2tf(rb[i].z));
            Bs[arow[i]][ak4[i]+3] = __uint_as_float(f2tf(rb[i].w));
        }
        __syncthreads();
        if (kc + 1 < CD / 16) {
            #pragma unroll
            for (int i = 0; i < 2; i++) {
                ra[i] = *(const float4*)(aptr[i] + (kc + 1) * 16);
                rb[i] = *(const float4*)(bptr[i] + (kc + 1) * 16);
            }
        }
        #pragma unroll
        for (int kk = 0; kk < 2; kk++) {
            unsigned a[2][4];
            #pragma unroll
            for (int mi = 0; mi < 2; mi++) {
                a[mi][0] = __float_as_uint(As[kk*8 + qd    ][wm + mi*16 + ql    ]);
                a[mi][1] = __float_as_uint(As[kk*8 + qd    ][wm + mi*16 + ql + 8]);
                a[mi][2] = __float_as_uint(As[kk*8 + qd + 4][wm + mi*16 + ql    ]);
                a[mi][3] = __float_as_uint(As[kk*8 + qd + 4][wm + mi*16 + ql + 8]);
            }
            #pragma unroll
            for (int nb = 0; nb < 8; nb++) {
                unsigned b0 = __float_as_uint(Bs[wn + nb*8 + ql][kk*8 + qd    ]);
                unsigned b1 = __float_as_uint(Bs[wn + nb*8 + ql][kk*8 + qd + 4]);
                mma_tf32(acc[0][nb], a[0], b0, b1);
                mma_tf32(acc[1][nb], a[1], b0, b1);
            }
        }
        __syncthreads();
    }

    #pragma unroll
    for (int mi = 0; mi < 2; mi++) {
        const int r0 = bm + wm + mi*16 + ql;
        #pragma unroll
        for (int nb = 0; nb < 8; nb++) {
            const int cidx = bn + wn + nb*8 + 2*qd;
            const float b0v = bp[cidx], b1v = bp[cidx + 1];
            *(float2*)(out + r0 * CD + cidx) =
                make_float2(acc[mi][nb][0] + b0v, acc[mi][nb][1] + b1v);
            *(float2*)(out + (r0 + 8) * CD + cidx) =
                make_float2(acc[mi][nb][2] + b0v, acc[mi][nb][3] + b1v);
        }
    }
}

// ---------------------------------------------------------------------------
extern "C" void kernel_launch(void* const* d_in, const int* in_sizes, int n_in,
                              void* d_out, int out_size) {
    const float* x  = (const float*)d_in[0];
    const float* Wk = (const float*)d_in[1];
    const float* Wv = (const float*)d_in[2];
    const float* Wq = (const float*)d_in[3];
    const float* Wp = (const float*)d_in[4];
    const float* bp = (const float*)d_in[5];
    float* out = (float*)d_out;
    (void)in_sizes; (void)n_in; (void)out_size;

    qkv_gemm_tc<<<dim3(9, 32), 256>>>(x, Wq, Wk, Wv);
    mqa_attn_tc<<<dim3(16, 32), 256>>>();
    out_gemm_tc<<<dim3(8, 32), 256>>>(Wp, bp, out);
}